// round 8
// baseline (speedup 1.0000x reference)
#include <cuda_runtime.h>
#include <cuda_bf16.h>

// HypAgg: hyperbolic graph aggregation (Poincare ball, c=1), N=1024, D=64.
// Inputs identified BY SIZE (order-agnostic): x[1024,64], adj[1024,1024],
// att_W[128,1], att_b[1]. Output: [1024,64] f32.
//
// Identity: logmap(x_i, x_j) = -alpha*x_i + beta*x_j with scalars
//   alpha = (1-2g+y2)/den, beta = (1-x2i)/den, den = 1-2g+x2i*y2, g = x_i.x_j
// so support_t[i] = -(sum w*alpha)*x_i + sum (w*beta)*x_j.
// NOTE the HGCN quirk: the final step is expmap(u=x, p=support_t), i.e.
// exp at the SUPPORT vector of tangent x, then proj.

#define NN 1024
#define DD 64
#define MIN_NORM 1e-15f
#define ART_CLIP (1.0f - 1e-7f)
#define MAXNORM (1.0f - 4e-3f)

__device__ float g_x2[NN];
__device__ float g_left[NN];
__device__ float g_right[NN];

// ---------------------------------------------------------------------------
// Kernel 1: per-row stats. One warp per row.
//   g_x2[r] = |x_r|^2 ; g_left/g_right = attention projections of logmap0(x_r)
// ---------------------------------------------------------------------------
__global__ void __launch_bounds__(256) hypagg_rows(
    const float* __restrict__ x, const float* __restrict__ W,
    const float* __restrict__ b)
{
    int r = blockIdx.x * 8 + (threadIdx.x >> 5);
    int lane = threadIdx.x & 31;
    const float* xr = x + r * DD;
    float x0 = xr[lane], x1 = xr[lane + 32];
    float x2p = x0 * x0 + x1 * x1;
    float w1p = x0 * W[lane] + x1 * W[lane + 32];
    float w2p = x0 * W[64 + lane] + x1 * W[96 + lane];
#pragma unroll
    for (int off = 16; off; off >>= 1) {
        x2p += __shfl_down_sync(0xffffffffu, x2p, off);
        w1p += __shfl_down_sync(0xffffffffu, w1p, off);
        w2p += __shfl_down_sync(0xffffffffu, w2p, off);
    }
    if (lane == 0) {
        float pn  = sqrtf(x2p);
        float pnc = fmaxf(pn, MIN_NORM);
        float z   = fminf(pn, ART_CLIP);
        float at  = 0.5f * __logf((1.0f + z) / (1.0f - z));  // artanh
        float tf  = at / pnc;
        g_x2[r]    = x2p;
        g_left[r]  = tf * w1p + b[0];
        g_right[r] = tf * w2p;
    }
}

// ---------------------------------------------------------------------------
// Kernel 2: one CTA (128 threads) per row i.
//  Phase B: each warp scans its own 256-column strip of adj, computes pair
//           scalars for nonzeros, ballot-compacts into its own shared segment.
//  Phase C: segment-ordered compacted GEMV (fixed FP order, deterministic).
//  Phase D: expmap(u = x_i, p = support_t) then proj.
// ---------------------------------------------------------------------------
__global__ void __launch_bounds__(128) hypagg_main(
    const float* __restrict__ x, const float* __restrict__ adj,
    float* __restrict__ out)
{
    __shared__ float s_xi[DD];
    __shared__ float s_cval[NN];
    __shared__ int   s_cidx[NN];
    __shared__ int   s_wcnt[4];
    __shared__ float s_acc[DD];
    __shared__ float s_red[4][2];

    int i = blockIdx.x;
    int t = threadIdx.x;
    int lane = t & 31, wid = t >> 5;

    if (t < 16)
        reinterpret_cast<float4*>(s_xi)[t] =
            reinterpret_cast<const float4*>(x + i * DD)[t];
    __syncthreads();

    float x2i = g_x2[i];
    float li  = g_left[i];
    float fac = fmaxf(1.0f - x2i, MIN_NORM);   // = 2/lambda_{x_i} (c=1)
    float wa_sum = 0.0f;                       // sum_j w*alpha  -> S_i
    int   wcnt   = 0;
    int   wbase  = wid * 256;

    // ---- Phase B: per-warp strip scan + compaction (8 x 32 columns) ----
#pragma unroll 1
    for (int c = 0; c < 8; ++c) {
        int j = wbase + c * 32 + lane;
        float a = adj[i * NN + j];
        bool pred = (a != 0.0f);
        float cv = 0.0f;
        if (pred) {
            const float4* xj = reinterpret_cast<const float4*>(x + j * DD);
            float g = 0.0f;
#pragma unroll
            for (int q = 0; q < 16; ++q) {
                float4 v = xj[q];
                g += v.x * s_xi[4*q] + v.y * s_xi[4*q+1]
                   + v.z * s_xi[4*q+2] + v.w * s_xi[4*q+3];
            }
            float y2  = g_x2[j];
            float A   = 1.0f - 2.0f * g + y2;
            float den = fmaxf(1.0f - 2.0f * g + x2i * y2, MIN_NORM);
            float inv = 1.0f / den;
            float alpha = A * inv;              // coeff on -x_i
            float beta  = (1.0f - x2i) * inv;   // coeff on  x_j
            float sn2 = fmaxf(alpha*alpha*x2i - 2.0f*alpha*beta*g
                              + beta*beta*y2, 0.0f);
            float sn  = fmaxf(sqrtf(sn2), MIN_NORM);
            float z   = fminf(sn, ART_CLIP);
            float at  = 0.5f * __logf((1.0f + z) / (1.0f - z));
            float wpre = fac * at / sn;
            float sarg = li + g_right[j];
            float att  = a / (1.0f + __expf(-sarg));  // sigmoid * adj
            float w = att * wpre;
            cv = w * beta;
            wa_sum += w * alpha;
        }
        unsigned m = __ballot_sync(0xffffffffu, pred);
        if (pred) {
            int pos = wbase + wcnt + __popc(m & ((1u << lane) - 1u));
            s_cidx[pos] = j;
            s_cval[pos] = cv;
        }
        wcnt += __popc(m);
    }
    if (lane == 0) s_wcnt[wid] = wcnt;

    // reduce S_i = sum w*alpha
#pragma unroll
    for (int off = 16; off; off >>= 1)
        wa_sum += __shfl_down_sync(0xffffffffu, wa_sum, off);
    if (lane == 0) s_red[wid][0] = wa_sum;
    __syncthreads();
    float S = s_red[0][0] + s_red[1][0] + s_red[2][0] + s_red[3][0];
    __syncthreads();

    // ---- Phase C: compacted GEMV over 4 segments (fixed order) ----
    int d = t & 63, half = t >> 6;
    float acc = 0.0f;
#pragma unroll 1
    for (int seg = 0; seg < 4; ++seg) {
        int base = seg * 256, cs = s_wcnt[seg];
        for (int k = half; k < cs; k += 2)
            acc += s_cval[base + k] * __ldg(x + s_cidx[base + k] * DD + d);
    }
    if (half == 0) s_acc[d] = acc;
    __syncthreads();
    if (half == 1) s_acc[d] += acc;
    __syncthreads();

    // ---- Phase D: expmap(u = x_i, p = sp) then proj ----
    // sp = support_t[i]; u = x_i. (HGCN argument order!)
    float xid = 0.0f, sp = 0.0f;
    if (t < 64) {
        xid = s_xi[d];
        sp  = s_acc[d] - S * xid;    // support_t[i][d]
    }
    float p1 = sp * sp, p2 = xid * sp;
#pragma unroll
    for (int off = 16; off; off >>= 1) {
        p1 += __shfl_down_sync(0xffffffffu, p1, off);
        p2 += __shfl_down_sync(0xffffffffu, p2, off);
    }
    if (lane == 0) { s_red[wid][0] = p1; s_red[wid][1] = p2; }
    __syncthreads();
    float sp2 = s_red[0][0] + s_red[1][0];   // |support|^2
    float spx = s_red[0][1] + s_red[1][1];   // support . x_i
    __syncthreads();   // everyone has read s_red before reuse below

    float un   = fmaxf(sqrtf(x2i), MIN_NORM);     // |u| = |x_i|
    float facp = fmaxf(1.0f - sp2, MIN_NORM);     // 2/lambda_p at p=support
    float arg  = un / facp;                       // sqrt_c*lam_p*|u|/2
    float th   = tanhf(arg);
    float sc   = th / un;                         // second = sc * x_i
    float y2e  = sc * sc * x2i;                   // |second|^2
    float xye  = sc * spx;                        // p . second
    float c1   = 1.0f + 2.0f * xye + y2e;         // coeff on p (= sp)
    float c2   = (1.0f - sp2) * sc;               // coeff on x_i
    float dene = fmaxf(1.0f + 2.0f * xye + sp2 * y2e, MIN_NORM);
    float res  = (c1 * sp + c2 * xid) / dene;

    float p3 = res * res;
#pragma unroll
    for (int off = 16; off; off >>= 1)
        p3 += __shfl_down_sync(0xffffffffu, p3, off);
    if (lane == 0) s_red[wid][0] = p3;
    __syncthreads();
    float r2 = s_red[0][0] + s_red[1][0];
    float n  = fmaxf(sqrtf(r2), MIN_NORM);
    float o  = (n > MAXNORM) ? res * (MAXNORM / n) : res;
    if (t < 64) out[i * DD + d] = o;
}

extern "C" void kernel_launch(void* const* d_in, const int* in_sizes, int n_in,
                              void* d_out, int out_size)
{
    // Order-agnostic input dispatch: the four inputs have unique sizes.
    const float *x = nullptr, *adj = nullptr, *W = nullptr, *b = nullptr;
    for (int k = 0; k < n_in; ++k) {
        switch (in_sizes[k]) {
            case NN * NN: adj = (const float*)d_in[k]; break;  // 1048576
            case NN * DD: x   = (const float*)d_in[k]; break;  // 65536
            case 2 * DD:  W   = (const float*)d_in[k]; break;  // 128
            case 1:       b   = (const float*)d_in[k]; break;  // 1
        }
    }
    float* out = (float*)d_out;
    (void)out_size;

    hypagg_rows<<<NN / 8, 256>>>(x, W, b);
    hypagg_main<<<NN, 128>>>(x, adj, out);
}